// round 16
// baseline (speedup 1.0000x reference)
#include <cuda_runtime.h>
#include <stdint.h>

#define WIN   442
#define NBINS 221
#define HOP   4
#define RELC  0.0594f
#define CWIN  448           // 558 blocks -> ONE wave at 4 blocks/SM (592 slots)
#define BATW  32            // windows per argmax batch (448 = 14 * 32)
#define RS    230           // mags row stride (even -> aligned float2 reads)
#define SEG   1024          // windows per scan segment (245 blocks > 148 SMs)
#define MAXWIN 262144
#define MAXSEG (MAXWIN / SEG)
#define CSCSZ (WIN + (WIN >> 4) + 1)   // skewed LUT size (442 + 27)

typedef unsigned long long u64;

__device__ u64   g_csc[WIN];                 // packed (cos, -sin)
__device__ int   g_bins[MAXWIN];
__device__ __align__(16) unsigned g_mapsP[MAXSEG * NBINS];
__device__ int2  g_segin[MAXSEG];

// ---------------------------------------------------------------------------
// Twiddle LUT: csc[m] = (cos(2pi m/442), -sin(2pi m/442)) packed, fp32.
// ---------------------------------------------------------------------------
__global__ void k_init_tables() {
    int m = threadIdx.x;
    if (m < WIN) {
        double ang = (2.0 * 3.141592653589793238462643 * (double)m) / (double)WIN;
        float c = (float)cos(ang), s = (float)sin(ang);
        g_csc[m] = ((u64)__float_as_uint(-s) << 32) | (u64)__float_as_uint(c);
    }
}

// ---------------------------------------------------------------------------
// Packed f32x2 primitives (lane0 = re, lane1 = im). Componentwise RN.
// ---------------------------------------------------------------------------
__device__ __forceinline__ u64 pk2(float lo, float hi) {
    u64 r; asm("mov.b64 %0, {%1, %2};" : "=l"(r) : "f"(lo), "f"(hi)); return r;
}
__device__ __forceinline__ void upk2(u64 v, float& lo, float& hi) {
    asm("mov.b64 {%0, %1}, %2;" : "=f"(lo), "=f"(hi) : "l"(v));
}
__device__ __forceinline__ u64 add2(u64 a, u64 b) {
    u64 r; asm("add.rn.f32x2 %0, %1, %2;" : "=l"(r) : "l"(a), "l"(b)); return r;
}
__device__ __forceinline__ u64 neg2(u64 a) { return a ^ 0x8000000080000000ull; }

// Kahan with negated compensation NC = -C (used only once per batch).
__device__ __forceinline__ void kaddn(u64& S, u64& NC, u64 P) {
    u64 y = add2(P, NC);
    u64 t = add2(S, y);
    NC = add2(add2(S, neg2(t)), y);
    S = t;
}

// skewed LUT index: breaks power-of-2-stride bank conflicts on the 8B table
__device__ __forceinline__ int sk(int m) { return m + (m >> 4); }

// ---------------------------------------------------------------------------
// DFT + argmax. Rotation-free + twiddle-factored + hierarchical accumulation
// + resynced twiddle recurrence + branch-free unrolled mainloop (R13) +
// PAIRWISE phase-2 argmax (float2 loads, exact tie->lowest-bin semantics).
// Numerics of phase 1 are byte-identical to R13.
// ---------------------------------------------------------------------------
__global__ __launch_bounds__(224, 4) void k_dft(const float* __restrict__ x, int n_win) {
    __shared__ __align__(16) float xs[WIN + 4 * CWIN];   // 2234 floats
    __shared__ __align__(16) float ds[4 * CWIN];         // per-window deltas
    __shared__ u64   csc[CSCSZ];
    __shared__ __align__(16) float mags[BATW * RS];      // 32 x 230
    __shared__ u64   pkeys[BATW * 7];

    const int tid = threadIdx.x;
    const int w0  = blockIdx.x * CWIN;
    const int nc  = min(CWIN, n_win - w0);
    const int s0  = w0 * HOP;
    const int L   = 4 * nc + 438;

    for (int i = tid; i < L; i += blockDim.x) xs[i] = x[s0 + i];
    for (int i = tid; i < WIN; i += blockDim.x) csc[sk(i)] = g_csc[i];
    __syncthreads();

    // deltas for valid slides; ZERO beyond so the mainloop is guard-free
    const int dvalid = 4 * (nc - 1);
    for (int i = tid; i < dvalid; i += blockDim.x)
        ds[i] = __fsub_rn(xs[i + 442], xs[i]);
    for (int i = dvalid + tid; i < 4 * CWIN; i += blockDim.x)
        ds[i] = 0.0f;

    const int kk = min(tid, NBINS - 1);       // clamp: tail lanes dup bin 220
    const int step8 = (32 * kk) % WIN;        // 8-window / 8-group advance

    // per-thread twiddle constants
    float e1r, e1i, e2r, e2i, e3r, e3i, e4r, e4i;
    upk2(csc[sk(kk)], e1r, e1i);
    upk2(csc[sk((2 * kk) % WIN)], e2r, e2i);
    upk2(csc[sk((3 * kk) % WIN)], e3r, e3i);
    upk2(csc[sk((4 * kk) % WIN)], e4r, e4i);  // E4 = e^{-i 4 th k}

    u64 YB = 0ull, NC = 0ull;                 // batch-level Kahan base
    u64 SL = 0ull;                            // within-batch plain sum

    // ---- direct DFT of window 0 (groups of 4 taps, recurrence twiddles) ----
    {
        int idx8 = 0;
        float tc = 1.0f, nsn = 0.0f;
        #pragma unroll 2
        for (int g = 0; g < 110; g++) {
            if ((g & 7) == 0) {               // resync from exact LUT
                upk2(csc[sk(idx8)], tc, nsn);
            }
            const float4 xv = *(const float4*)&xs[4 * g];
            float Zr = __fmaf_rn(xv.w, e3r, __fmaf_rn(xv.z, e2r, __fmaf_rn(xv.y, e1r, xv.x)));
            float Zi = __fmaf_rn(xv.w, e3i, __fmaf_rn(xv.z, e2i, __fmul_rn(xv.y, e1i)));
            float Dre = __fmaf_rn(-Zi, nsn, __fmul_rn(Zr, tc));
            float Dim = __fmaf_rn( Zi, tc,  __fmul_rn(Zr, nsn));
            kaddn(YB, NC, pk2(Dre, Dim));
            float ntc = __fmaf_rn(-nsn, e4i, __fmul_rn(tc, e4r));
            float nns = __fmaf_rn( nsn, e4r, __fmul_rn(tc, e4i));
            tc = ntc; nsn = nns;
            if ((g & 7) == 7) {
                idx8 += step8; if (idx8 >= WIN) idx8 -= WIN;
            }
        }
        {   // tail taps n = 440, 441 use T_110 (<=6 drift steps)
            float x0 = xs[440], x1 = xs[441];
            float Zr = __fmaf_rn(x1, e1r, x0);
            float Zi = __fmul_rn(x1, e1i);
            float Dre = __fmaf_rn(-Zi, nsn, __fmul_rn(Zr, tc));
            float Dim = __fmaf_rn( Zi, tc,  __fmul_rn(Zr, nsn));
            kaddn(YB, NC, pk2(Dre, Dim));
        }
    }
    __syncthreads();                           // ds ready for all threads

    int idx8 = 0;                              // window-frame resync index
    for (int b0 = 0; b0 < CWIN; b0 += BATW) {
        // ---- phase 1: branch-free, fully unrolled 8-window chunks ----
        const u64 YBc = add2(YB, NC);          // batch-invariant corrected base
        float* mrow = &mags[tid];
        #pragma unroll
        for (int w8 = 0; w8 < BATW; w8 += 8) {
            float tc, nsn;
            upk2(csc[sk(idx8)], tc, nsn);      // exact resync, hoisted
            #pragma unroll
            for (int j = 0; j < 8; j++) {
                const int w = b0 + w8 + j;

                u64 Yc = add2(YBc, SL);
                float yr, yi;  upk2(Yc, yr, yi);
                float xr = __fmaf_rn(yi, nsn, __fmul_rn(yr, tc));
                float xi = __fmaf_rn(yi, tc, -__fmul_rn(yr, nsn));
                mrow[(w8 + j) * RS] = __fadd_rn(fabsf(xr), fabsf(xi));

                const float4 d = *(const float4*)&ds[4 * w];
                float Zr = __fmaf_rn(d.w, e3r, __fmaf_rn(d.z, e2r, __fmaf_rn(d.y, e1r, d.x)));
                float Zi = __fmaf_rn(d.w, e3i, __fmaf_rn(d.z, e2i, __fmul_rn(d.y, e1i)));
                float Dre = __fmaf_rn(-Zi, nsn, __fmul_rn(Zr, tc));
                float Dim = __fmaf_rn( Zi, tc,  __fmul_rn(Zr, nsn));
                SL = add2(SL, pk2(Dre, Dim));

                float ntc = __fmaf_rn(-nsn, e4i, __fmul_rn(tc, e4r));
                float nns = __fmaf_rn( nsn, e4r, __fmul_rn(tc, e4i));
                tc = ntc; nsn = nns;           // dead at j=7 -> DCE'd
            }
            idx8 += step8; if (idx8 >= WIN) idx8 -= WIN;
        }
        // fold batch total into the Kahan base; reset local sum
        kaddn(YB, NC, SL);
        SL = 0ull;
        __syncthreads();

        // ---- phase 2: pairwise partial argmax; part = warp (tid>>5) ----
        {
            const int win  = tid & 31;
            const int part = tid >> 5;           // 0..6, all 224 threads
            const int kbeg = part * 32;
            const int kend = min(kbeg + 32, NBINS);
            const float* row = &mags[win * RS];
            float best = -1.0f;
            int   bbin = kbeg;
            // ascending pairwise scan; strict > and intra-pair >= keep
            // exact ties->lowest-bin (jnp.argmax) semantics
            for (int kx = kbeg; kx + 1 < kend; kx += 2) {
                const float2 v = *(const float2*)&row[kx];
                float m = fmaxf(v.x, v.y);
                if (m > best) { best = m; bbin = (v.x >= m) ? kx : kx + 1; }
            }
            if ((kend - kbeg) & 1) {             // odd tail (part 6 only)
                float v = row[kend - 1];
                if (v > best) { best = v; bbin = kend - 1; }
            }
            pkeys[win * 7 + part] =
                (((u64)__float_as_uint(best)) << 32)
                | (u64)(0xFFFFFFFFu - (unsigned)bbin);
        }
        __syncthreads();

        // ---- merge 7 partials per window (packed-key max: ties -> low bin)
        if (tid < BATW && b0 + tid < nc) {
            u64 m = pkeys[tid * 7];
            #pragma unroll
            for (int j = 1; j < 7; j++) {
                u64 v = pkeys[tid * 7 + j];
                if (v > m) m = v;
            }
            g_bins[w0 + b0 + tid] = (int)(0xFFFFFFFFu - (unsigned)(m & 0xFFFFFFFFull));
        }
        __syncthreads();
    }
}

// ---------------------------------------------------------------------------
// Scan phase 1: per-segment transition maps, written PACKED:
// (global_reset_time << 8) | bin, sentinel 0xFFFFFFFF = state survives.
// SEG=1024 -> 245 blocks (all SMs busy), 10 pointer-jump rounds.
// ---------------------------------------------------------------------------
__global__ void k_segmaps(int n_win) {
    __shared__ int   sb[SEG];
    __shared__ short sj[SEG];
    const int seg = blockIdx.x;
    const int s0  = seg * SEG;
    const int len = min(SEG, n_win - s0);

    for (int i = threadIdx.x; i < SEG; i += blockDim.x)
        sb[i] = (i < len) ? g_bins[s0 + i] : 0;
    __syncthreads();

    for (int p = threadIdx.x; p < len; p += blockDim.x) {
        float F   = 100.0f * (float)sb[p];
        float thr = F * RELC;
        int j = p + 1;
        while (j < len && fabsf(F - 100.0f * (float)sb[j]) <= thr) j++;
        sj[p] = (short)((j < len) ? j : p);      // self-loop == terminal
    }
    __syncthreads();

    for (int r = 0; r < 10; r++) {               // log2(1024) rounds
        for (int p = threadIdx.x; p < len; p += blockDim.x)
            sj[p] = sj[sj[p]];
        __syncthreads();
    }

    for (int f = threadIdx.x; f < NBINS; f += blockDim.x) {
        float F   = 100.0f * (float)f;
        float thr = F * RELC;
        int j = 0;
        while (j < len && fabsf(F - 100.0f * (float)sb[j]) <= thr) j++;
        unsigned v;
        if (j >= len) v = 0xFFFFFFFFu;
        else { int term = sj[j]; v = (((unsigned)(s0 + term)) << 8) | (unsigned)sb[term]; }
        g_mapsP[seg * NBINS + f] = v;
    }
}

// ---------------------------------------------------------------------------
// Scan phase 2: bulk-load packed maps (~217 KB) with wide uint4 loads and
// 1024 threads (deep MLP), then thread 0 walks the chain in shared memory.
// ---------------------------------------------------------------------------
__global__ void k_walk(int n_win, int nseg, float* __restrict__ out) {
    extern __shared__ unsigned sm[];
    const int tot  = nseg * NBINS;
    const int tot4 = tot >> 2;
    const uint4* src4 = (const uint4*)g_mapsP;
    uint4* dst4 = (uint4*)sm;
    for (int i = threadIdx.x; i < tot4; i += blockDim.x) dst4[i] = src4[i];
    for (int i = (tot4 << 2) + threadIdx.x; i < tot; i += blockDim.x) sm[i] = g_mapsP[i];
    __syncthreads();

    if (threadIdx.x == 0) {
        int bF = 0, Tw = 0;
        for (int s = 0; s < nseg; s++) {
            g_segin[s] = make_int2(bF, Tw);
            unsigned v = sm[s * NBINS + bF];
            if (v != 0xFFFFFFFFu) { bF = (int)(v & 0xFFu); Tw = (int)(v >> 8); }
        }
        float F    = 100.0f * (float)bF;
        float Ft   = 4.0f * (float)Tw;
        float last = 4.0f * (float)(n_win - 1);
        out[3 * n_win + 0] = F;
        out[3 * n_win + 1] = __fdiv_rn((last - Ft) * 1000.0f, 44100.0f);
    }
}

// ---------------------------------------------------------------------------
// Scan phase 3: parallel fill with next-chunk prefetch. One warp per segment
// replays the exact reference emit semantics via ballots.
// ---------------------------------------------------------------------------
__global__ void k_fill(int n_win, float* __restrict__ out) {
    const int seg = blockIdx.x;
    const int s0  = seg * SEG;
    const int len = min(SEG, n_win - s0);
    const int lane = threadIdx.x;

    int2 st0 = g_segin[seg];
    float F = 100.0f * (float)st0.x;
    float T = 4.0f * (float)st0.y;

    float* flags = out;
    float* freqs = out + n_win;
    float* durs  = out + 2 * n_win;

    float tcur = (lane < len) ? 100.0f * (float)g_bins[s0 + lane] : 0.0f;

    for (int base = 0; base < len; base += 32) {
        // prefetch next chunk before the serial ballot chain
        const int nb = base + 32;
        float tnext = ((nb + lane) < len) ? 100.0f * (float)g_bins[s0 + nb + lane] : 0.0f;

        int  i     = s0 + base + lane;
        bool valid = (base + lane) < len;
        float t = tcur;

        unsigned rem = __ballot_sync(0xffffffffu, valid);
        float myF = 0.f, myT = 0.f;
        bool  myc = false;
        while (rem) {
            bool oob = fabsf(F - t) > F * RELC;
            unsigned bal = __ballot_sync(0xffffffffu, oob) & rem;
            if (!bal) {
                if (rem & (1u << lane)) { myF = F; myT = T; }
                break;
            }
            int e = __ffs(bal) - 1;
            if ((rem & (1u << lane)) && lane <= e) {
                myF = F; myT = T; myc = (lane == e);
            }
            F = __shfl_sync(0xffffffffu, t, e);
            T = 4.0f * (float)(s0 + base + e);
            unsigned below = (e == 31) ? 0xffffffffu : ((1u << (e + 1)) - 1u);
            rem &= ~below;
        }
        if (valid) {
            flags[i] = myc ? 1.0f : 0.0f;
            freqs[i] = myF;
            durs[i]  = __fdiv_rn(((float)(4 * i) - myT) * 1000.0f, 44100.0f);
        }
        tcur = tnext;
    }
}

// ---------------------------------------------------------------------------
extern "C" void kernel_launch(void* const* d_in, const int* in_sizes, int n_in,
                              void* d_out, int out_size) {
    const float* x = (const float*)d_in[0];
    int n     = in_sizes[0];
    int n_win = (n - WIN + HOP - 1) / HOP;
    if (n_win > MAXWIN) n_win = MAXWIN;   // safety cap (fixed input: 249890)
    int nblk = (n_win + CWIN - 1) / CWIN;
    int nseg = (n_win + SEG - 1) / SEG;
    float* out = (float*)d_out;

    size_t walk_smem = (size_t)nseg * NBINS * sizeof(unsigned);  // ~217 KB
    static bool attr_done = false;
    if (!attr_done) {
        cudaFuncSetAttribute(k_walk, cudaFuncAttributeMaxDynamicSharedMemorySize,
                             (int)(220 * 1024));
        attr_done = true;
    }

    k_init_tables<<<1, 448>>>();
    k_dft<<<nblk, 224>>>(x, n_win);
    k_segmaps<<<nseg, 256>>>(n_win);
    k_walk<<<1, 1024, walk_smem>>>(n_win, nseg, out);
    k_fill<<<nseg, 32>>>(n_win, out);
}

// round 17
// speedup vs baseline: 1.0023x; 1.0023x over previous
#include <cuda_runtime.h>
#include <stdint.h>

#define WIN   442
#define NBINS 221
#define HOP   4
#define RELC  0.0594f
#define CWIN  448           // 558 blocks -> ONE wave at 4 blocks/SM (592 slots)
#define BATW  32            // windows per argmax batch (448 = 14 * 32)
#define RS    230           // mags row stride (even -> aligned float2 reads)
#define SEG   1024          // windows per scan segment (245 blocks > 148 SMs)
#define MAXWIN 262144
#define MAXSEG (MAXWIN / SEG)
#define CSCSZ (WIN + (WIN >> 4) + 1)   // skewed LUT size (442 + 27)

typedef unsigned long long u64;

__device__ u64   g_csc[WIN];                 // packed (cos, -sin)
__device__ int   g_bins[MAXWIN];
__device__ __align__(16) unsigned g_mapsP[MAXSEG * NBINS];
__device__ int2  g_segin[MAXSEG];

// ---------------------------------------------------------------------------
// Twiddle LUT: csc[m] = (cos(2pi m/442), -sin(2pi m/442)) packed, fp32.
// ---------------------------------------------------------------------------
__global__ void k_init_tables() {
    int m = threadIdx.x;
    if (m < WIN) {
        double ang = (2.0 * 3.141592653589793238462643 * (double)m) / (double)WIN;
        float c = (float)cos(ang), s = (float)sin(ang);
        g_csc[m] = ((u64)__float_as_uint(-s) << 32) | (u64)__float_as_uint(c);
    }
}

// ---------------------------------------------------------------------------
// Packed f32x2 primitives (lane0 = re, lane1 = im). Componentwise RN.
// ---------------------------------------------------------------------------
__device__ __forceinline__ u64 pk2(float lo, float hi) {
    u64 r; asm("mov.b64 %0, {%1, %2};" : "=l"(r) : "f"(lo), "f"(hi)); return r;
}
__device__ __forceinline__ void upk2(u64 v, float& lo, float& hi) {
    asm("mov.b64 {%0, %1}, %2;" : "=f"(lo), "=f"(hi) : "l"(v));
}
__device__ __forceinline__ u64 add2(u64 a, u64 b) {
    u64 r; asm("add.rn.f32x2 %0, %1, %2;" : "=l"(r) : "l"(a), "l"(b)); return r;
}
__device__ __forceinline__ u64 neg2(u64 a) { return a ^ 0x8000000080000000ull; }

// Kahan with negated compensation NC = -C (used only once per batch).
__device__ __forceinline__ void kaddn(u64& S, u64& NC, u64 P) {
    u64 y = add2(P, NC);
    u64 t = add2(S, y);
    NC = add2(add2(S, neg2(t)), y);
    S = t;
}

// skewed LUT index: breaks power-of-2-stride bank conflicts on the 8B table
__device__ __forceinline__ int sk(int m) { return m + (m >> 4); }

// ---------------------------------------------------------------------------
// DFT + argmax. Rotation-free + twiddle-factored + hierarchical accumulation
// + resynced twiddle recurrence + branch-free unrolled mainloop (R13) +
// PAIRWISE phase-2 argmax (float2 loads, exact tie->lowest-bin semantics).
// Numerics of phase 1 are byte-identical to R13.
// ---------------------------------------------------------------------------
__global__ __launch_bounds__(224, 4) void k_dft(const float* __restrict__ x, int n_win) {
    __shared__ __align__(16) float xs[WIN + 4 * CWIN];   // 2234 floats
    __shared__ __align__(16) float ds[4 * CWIN];         // per-window deltas
    __shared__ u64   csc[CSCSZ];
    __shared__ __align__(16) float mags[BATW * RS];      // 32 x 230
    __shared__ u64   pkeys[BATW * 7];

    const int tid = threadIdx.x;
    const int w0  = blockIdx.x * CWIN;
    const int nc  = min(CWIN, n_win - w0);
    const int s0  = w0 * HOP;
    const int L   = 4 * nc + 438;

    for (int i = tid; i < L; i += blockDim.x) xs[i] = x[s0 + i];
    for (int i = tid; i < WIN; i += blockDim.x) csc[sk(i)] = g_csc[i];
    __syncthreads();

    // deltas for valid slides; ZERO beyond so the mainloop is guard-free
    const int dvalid = 4 * (nc - 1);
    for (int i = tid; i < dvalid; i += blockDim.x)
        ds[i] = __fsub_rn(xs[i + 442], xs[i]);
    for (int i = dvalid + tid; i < 4 * CWIN; i += blockDim.x)
        ds[i] = 0.0f;

    const int kk = min(tid, NBINS - 1);       // clamp: tail lanes dup bin 220
    const int step8 = (32 * kk) % WIN;        // 8-window / 8-group advance

    // per-thread twiddle constants
    float e1r, e1i, e2r, e2i, e3r, e3i, e4r, e4i;
    upk2(csc[sk(kk)], e1r, e1i);
    upk2(csc[sk((2 * kk) % WIN)], e2r, e2i);
    upk2(csc[sk((3 * kk) % WIN)], e3r, e3i);
    upk2(csc[sk((4 * kk) % WIN)], e4r, e4i);  // E4 = e^{-i 4 th k}

    u64 YB = 0ull, NC = 0ull;                 // batch-level Kahan base
    u64 SL = 0ull;                            // within-batch plain sum

    // ---- direct DFT of window 0 (groups of 4 taps, recurrence twiddles) ----
    {
        int idx8 = 0;
        float tc = 1.0f, nsn = 0.0f;
        #pragma unroll 2
        for (int g = 0; g < 110; g++) {
            if ((g & 7) == 0) {               // resync from exact LUT
                upk2(csc[sk(idx8)], tc, nsn);
            }
            const float4 xv = *(const float4*)&xs[4 * g];
            float Zr = __fmaf_rn(xv.w, e3r, __fmaf_rn(xv.z, e2r, __fmaf_rn(xv.y, e1r, xv.x)));
            float Zi = __fmaf_rn(xv.w, e3i, __fmaf_rn(xv.z, e2i, __fmul_rn(xv.y, e1i)));
            float Dre = __fmaf_rn(-Zi, nsn, __fmul_rn(Zr, tc));
            float Dim = __fmaf_rn( Zi, tc,  __fmul_rn(Zr, nsn));
            kaddn(YB, NC, pk2(Dre, Dim));
            float ntc = __fmaf_rn(-nsn, e4i, __fmul_rn(tc, e4r));
            float nns = __fmaf_rn( nsn, e4r, __fmul_rn(tc, e4i));
            tc = ntc; nsn = nns;
            if ((g & 7) == 7) {
                idx8 += step8; if (idx8 >= WIN) idx8 -= WIN;
            }
        }
        {   // tail taps n = 440, 441 use T_110 (<=6 drift steps)
            float x0 = xs[440], x1 = xs[441];
            float Zr = __fmaf_rn(x1, e1r, x0);
            float Zi = __fmul_rn(x1, e1i);
            float Dre = __fmaf_rn(-Zi, nsn, __fmul_rn(Zr, tc));
            float Dim = __fmaf_rn( Zi, tc,  __fmul_rn(Zr, nsn));
            kaddn(YB, NC, pk2(Dre, Dim));
        }
    }
    __syncthreads();                           // ds ready for all threads

    int idx8 = 0;                              // window-frame resync index
    for (int b0 = 0; b0 < CWIN; b0 += BATW) {
        // ---- phase 1: branch-free, fully unrolled 8-window chunks ----
        const u64 YBc = add2(YB, NC);          // batch-invariant corrected base
        float* mrow = &mags[tid];
        #pragma unroll
        for (int w8 = 0; w8 < BATW; w8 += 8) {
            float tc, nsn;
            upk2(csc[sk(idx8)], tc, nsn);      // exact resync, hoisted
            #pragma unroll
            for (int j = 0; j < 8; j++) {
                const int w = b0 + w8 + j;

                u64 Yc = add2(YBc, SL);
                float yr, yi;  upk2(Yc, yr, yi);
                float xr = __fmaf_rn(yi, nsn, __fmul_rn(yr, tc));
                float xi = __fmaf_rn(yi, tc, -__fmul_rn(yr, nsn));
                mrow[(w8 + j) * RS] = __fadd_rn(fabsf(xr), fabsf(xi));

                const float4 d = *(const float4*)&ds[4 * w];
                float Zr = __fmaf_rn(d.w, e3r, __fmaf_rn(d.z, e2r, __fmaf_rn(d.y, e1r, d.x)));
                float Zi = __fmaf_rn(d.w, e3i, __fmaf_rn(d.z, e2i, __fmul_rn(d.y, e1i)));
                float Dre = __fmaf_rn(-Zi, nsn, __fmul_rn(Zr, tc));
                float Dim = __fmaf_rn( Zi, tc,  __fmul_rn(Zr, nsn));
                SL = add2(SL, pk2(Dre, Dim));

                float ntc = __fmaf_rn(-nsn, e4i, __fmul_rn(tc, e4r));
                float nns = __fmaf_rn( nsn, e4r, __fmul_rn(tc, e4i));
                tc = ntc; nsn = nns;           // dead at j=7 -> DCE'd
            }
            idx8 += step8; if (idx8 >= WIN) idx8 -= WIN;
        }
        // fold batch total into the Kahan base; reset local sum
        kaddn(YB, NC, SL);
        SL = 0ull;
        __syncthreads();

        // ---- phase 2: pairwise partial argmax; part = warp (tid>>5) ----
        {
            const int win  = tid & 31;
            const int part = tid >> 5;           // 0..6, all 224 threads
            const int kbeg = part * 32;
            const int kend = min(kbeg + 32, NBINS);
            const float* row = &mags[win * RS];
            float best = -1.0f;
            int   bbin = kbeg;
            // ascending pairwise scan; strict > and intra-pair >= keep
            // exact ties->lowest-bin (jnp.argmax) semantics
            for (int kx = kbeg; kx + 1 < kend; kx += 2) {
                const float2 v = *(const float2*)&row[kx];
                float m = fmaxf(v.x, v.y);
                if (m > best) { best = m; bbin = (v.x >= m) ? kx : kx + 1; }
            }
            if ((kend - kbeg) & 1) {             // odd tail (part 6 only)
                float v = row[kend - 1];
                if (v > best) { best = v; bbin = kend - 1; }
            }
            pkeys[win * 7 + part] =
                (((u64)__float_as_uint(best)) << 32)
                | (u64)(0xFFFFFFFFu - (unsigned)bbin);
        }
        __syncthreads();

        // ---- merge 7 partials per window (packed-key max: ties -> low bin)
        if (tid < BATW && b0 + tid < nc) {
            u64 m = pkeys[tid * 7];
            #pragma unroll
            for (int j = 1; j < 7; j++) {
                u64 v = pkeys[tid * 7 + j];
                if (v > m) m = v;
            }
            g_bins[w0 + b0 + tid] = (int)(0xFFFFFFFFu - (unsigned)(m & 0xFFFFFFFFull));
        }
        __syncthreads();
    }
}

// ---------------------------------------------------------------------------
// Scan phase 1: per-segment transition maps, written PACKED:
// (global_reset_time << 8) | bin, sentinel 0xFFFFFFFF = state survives.
// SEG=1024 -> 245 blocks (all SMs busy), 10 pointer-jump rounds.
// ---------------------------------------------------------------------------
__global__ void k_segmaps(int n_win) {
    __shared__ int   sb[SEG];
    __shared__ short sj[SEG];
    const int seg = blockIdx.x;
    const int s0  = seg * SEG;
    const int len = min(SEG, n_win - s0);

    for (int i = threadIdx.x; i < SEG; i += blockDim.x)
        sb[i] = (i < len) ? g_bins[s0 + i] : 0;
    __syncthreads();

    for (int p = threadIdx.x; p < len; p += blockDim.x) {
        float F   = 100.0f * (float)sb[p];
        float thr = F * RELC;
        int j = p + 1;
        while (j < len && fabsf(F - 100.0f * (float)sb[j]) <= thr) j++;
        sj[p] = (short)((j < len) ? j : p);      // self-loop == terminal
    }
    __syncthreads();

    for (int r = 0; r < 10; r++) {               // log2(1024) rounds
        for (int p = threadIdx.x; p < len; p += blockDim.x)
            sj[p] = sj[sj[p]];
        __syncthreads();
    }

    for (int f = threadIdx.x; f < NBINS; f += blockDim.x) {
        float F   = 100.0f * (float)f;
        float thr = F * RELC;
        int j = 0;
        while (j < len && fabsf(F - 100.0f * (float)sb[j]) <= thr) j++;
        unsigned v;
        if (j >= len) v = 0xFFFFFFFFu;
        else { int term = sj[j]; v = (((unsigned)(s0 + term)) << 8) | (unsigned)sb[term]; }
        g_mapsP[seg * NBINS + f] = v;
    }
}

// ---------------------------------------------------------------------------
// Scan phase 2: bulk-load packed maps (~217 KB) with wide uint4 loads and
// 1024 threads (deep MLP), then thread 0 walks the chain in shared memory.
// ---------------------------------------------------------------------------
__global__ void k_walk(int n_win, int nseg, float* __restrict__ out) {
    extern __shared__ unsigned sm[];
    const int tot  = nseg * NBINS;
    const int tot4 = tot >> 2;
    const uint4* src4 = (const uint4*)g_mapsP;
    uint4* dst4 = (uint4*)sm;
    for (int i = threadIdx.x; i < tot4; i += blockDim.x) dst4[i] = src4[i];
    for (int i = (tot4 << 2) + threadIdx.x; i < tot; i += blockDim.x) sm[i] = g_mapsP[i];
    __syncthreads();

    if (threadIdx.x == 0) {
        int bF = 0, Tw = 0;
        for (int s = 0; s < nseg; s++) {
            g_segin[s] = make_int2(bF, Tw);
            unsigned v = sm[s * NBINS + bF];
            if (v != 0xFFFFFFFFu) { bF = (int)(v & 0xFFu); Tw = (int)(v >> 8); }
        }
        float F    = 100.0f * (float)bF;
        float Ft   = 4.0f * (float)Tw;
        float last = 4.0f * (float)(n_win - 1);
        out[3 * n_win + 0] = F;
        out[3 * n_win + 1] = __fdiv_rn((last - Ft) * 1000.0f, 44100.0f);
    }
}

// ---------------------------------------------------------------------------
// Scan phase 3: parallel fill with next-chunk prefetch. One warp per segment
// replays the exact reference emit semantics via ballots.
// ---------------------------------------------------------------------------
__global__ void k_fill(int n_win, float* __restrict__ out) {
    const int seg = blockIdx.x;
    const int s0  = seg * SEG;
    const int len = min(SEG, n_win - s0);
    const int lane = threadIdx.x;

    int2 st0 = g_segin[seg];
    float F = 100.0f * (float)st0.x;
    float T = 4.0f * (float)st0.y;

    float* flags = out;
    float* freqs = out + n_win;
    float* durs  = out + 2 * n_win;

    float tcur = (lane < len) ? 100.0f * (float)g_bins[s0 + lane] : 0.0f;

    for (int base = 0; base < len; base += 32) {
        // prefetch next chunk before the serial ballot chain
        const int nb = base + 32;
        float tnext = ((nb + lane) < len) ? 100.0f * (float)g_bins[s0 + nb + lane] : 0.0f;

        int  i     = s0 + base + lane;
        bool valid = (base + lane) < len;
        float t = tcur;

        unsigned rem = __ballot_sync(0xffffffffu, valid);
        float myF = 0.f, myT = 0.f;
        bool  myc = false;
        while (rem) {
            bool oob = fabsf(F - t) > F * RELC;
            unsigned bal = __ballot_sync(0xffffffffu, oob) & rem;
            if (!bal) {
                if (rem & (1u << lane)) { myF = F; myT = T; }
                break;
            }
            int e = __ffs(bal) - 1;
            if ((rem & (1u << lane)) && lane <= e) {
                myF = F; myT = T; myc = (lane == e);
            }
            F = __shfl_sync(0xffffffffu, t, e);
            T = 4.0f * (float)(s0 + base + e);
            unsigned below = (e == 31) ? 0xffffffffu : ((1u << (e + 1)) - 1u);
            rem &= ~below;
        }
        if (valid) {
            flags[i] = myc ? 1.0f : 0.0f;
            freqs[i] = myF;
            durs[i]  = __fdiv_rn(((float)(4 * i) - myT) * 1000.0f, 44100.0f);
        }
        tcur = tnext;
    }
}

// ---------------------------------------------------------------------------
extern "C" void kernel_launch(void* const* d_in, const int* in_sizes, int n_in,
                              void* d_out, int out_size) {
    const float* x = (const float*)d_in[0];
    int n     = in_sizes[0];
    int n_win = (n - WIN + HOP - 1) / HOP;
    if (n_win > MAXWIN) n_win = MAXWIN;   // safety cap (fixed input: 249890)
    int nblk = (n_win + CWIN - 1) / CWIN;
    int nseg = (n_win + SEG - 1) / SEG;
    float* out = (float*)d_out;

    size_t walk_smem = (size_t)nseg * NBINS * sizeof(unsigned);  // ~217 KB
    static bool attr_done = false;
    if (!attr_done) {
        cudaFuncSetAttribute(k_walk, cudaFuncAttributeMaxDynamicSharedMemorySize,
                             (int)(220 * 1024));
        attr_done = true;
    }

    k_init_tables<<<1, 448>>>();
    k_dft<<<nblk, 224>>>(x, n_win);
    k_segmaps<<<nseg, 256>>>(n_win);
    k_walk<<<1, 1024, walk_smem>>>(n_win, nseg, out);
    k_fill<<<nseg, 32>>>(n_win, out);
}